// round 14
// baseline (speedup 1.0000x reference)
#include <cuda_runtime.h>

#define T_STEPS 2048
#define B_SZ    64
#define H_SZ    256
#define G3      768
#define BH      (B_SZ * H_SZ)
#define M_TOT   (T_STEPS * B_SZ)
#define NCHUNK  16
#define CHUNK_T (T_STEPS / NCHUNK)     // 128
#define CHUNK_M (CHUNK_T * B_SZ)       // 8192

typedef unsigned long long u64;

__device__ float g_gx[(size_t)M_TOT * G3];
__device__ float g_seqA[(size_t)T_STEPS * BH];
__device__ float g_seqB[(size_t)T_STEPS * BH];
struct PaddedCtr { unsigned int v; unsigned int pad[31]; };
__device__ PaddedCtr g_bar[3][2];

__global__ void reset_kernel() {
    int i = threadIdx.x;
    if (i < 6) g_bar[i >> 1][i & 1].v = 0u;
}

__device__ __forceinline__ void ffma2(u64 &d, u64 a, u64 b) {
    asm("fma.rn.f32x2 %0, %1, %2, %0;" : "+l"(d) : "l"(a), "l"(b));
}
__device__ __forceinline__ u64 pack2(float lo, float hi) {
    u64 r; asm("mov.b64 %0, {%1, %2};" : "=l"(r) : "f"(lo), "f"(hi)); return r;
}
__device__ __forceinline__ float2 unpack2(u64 v) {
    float2 r; asm("mov.b64 {%0, %1}, %2;" : "=f"(r.x), "=f"(r.y) : "l"(v)); return r;
}
__device__ __forceinline__ float fsigmoid(float x) {
    float e; asm("ex2.approx.f32 %0, %1;" : "=f"(e) : "f"(-1.4426950408889634f * x));
    float r; asm("rcp.approx.f32 %0, %1;" : "=f"(r) : "f"(1.0f + e));
    return r;
}
__device__ __forceinline__ float ftanh(float x) {
    float y; asm("tanh.approx.f32 %0, %1;" : "=f"(y) : "f"(x)); return y;
}

// ---------------- Phase A: gx GEMM (FFMA2, chunked) --------------------------
__global__ __launch_bounds__(256) void gemm_gx(
    const float* __restrict__ A, const float* __restrict__ W,
    const float* __restrict__ bias, int m_base)
{
    __shared__ __align__(16) float As[32 * 132];
    __shared__ __align__(16) float Bs[32 * 64];
    const int tid = threadIdx.x, tx = tid & 15, ty = tid >> 4;
    const int m0 = m_base + blockIdx.x * 128, n0 = blockIdx.y * 64;

    u64 acc[4][4];
#pragma unroll
    for (int i = 0; i < 4; i++)
#pragma unroll
        for (int j = 0; j < 4; j++) acc[i][j] = 0ULL;

    for (int k0 = 0; k0 < 256; k0 += 32) {
#pragma unroll
        for (int i = 0; i < 4; i++) {
            int f = tid + 256 * i, r = f >> 3, c4 = f & 7;
            float4 v = *(const float4*)(A + (size_t)(m0 + r) * 256 + k0 + c4 * 4);
            As[(c4 * 4 + 0) * 132 + r] = v.x;
            As[(c4 * 4 + 1) * 132 + r] = v.y;
            As[(c4 * 4 + 2) * 132 + r] = v.z;
            As[(c4 * 4 + 3) * 132 + r] = v.w;
        }
#pragma unroll
        for (int i = 0; i < 2; i++) {
            int f = tid + 256 * i, r = f >> 3, c4 = f & 7;
            float4 v = *(const float4*)(W + (size_t)(n0 + r) * 256 + k0 + c4 * 4);
            Bs[(c4 * 4 + 0) * 64 + r] = v.x;
            Bs[(c4 * 4 + 1) * 64 + r] = v.y;
            Bs[(c4 * 4 + 2) * 64 + r] = v.z;
            Bs[(c4 * 4 + 3) * 64 + r] = v.w;
        }
        __syncthreads();
#pragma unroll
        for (int k = 0; k < 32; k++) {
            const u64* ap = (const u64*)&As[k * 132 + ty * 8];
            u64 a0 = ap[0], a1 = ap[1], a2 = ap[2], a3 = ap[3];
            float4 bv = *(const float4*)&Bs[k * 64 + tx * 4];
            u64 b0 = pack2(bv.x, bv.x), b1 = pack2(bv.y, bv.y);
            u64 b2 = pack2(bv.z, bv.z), b3 = pack2(bv.w, bv.w);
            ffma2(acc[0][0], a0, b0); ffma2(acc[0][1], a0, b1);
            ffma2(acc[0][2], a0, b2); ffma2(acc[0][3], a0, b3);
            ffma2(acc[1][0], a1, b0); ffma2(acc[1][1], a1, b1);
            ffma2(acc[1][2], a1, b2); ffma2(acc[1][3], a1, b3);
            ffma2(acc[2][0], a2, b0); ffma2(acc[2][1], a2, b1);
            ffma2(acc[2][2], a2, b2); ffma2(acc[2][3], a2, b3);
            ffma2(acc[3][0], a3, b0); ffma2(acc[3][1], a3, b1);
            ffma2(acc[3][2], a3, b2); ffma2(acc[3][3], a3, b3);
        }
        __syncthreads();
    }
    float4 bv = *(const float4*)(bias + n0 + tx * 4);
#pragma unroll
    for (int i = 0; i < 4; i++) {
        float2 c0 = unpack2(acc[i][0]), c1 = unpack2(acc[i][1]);
        float2 c2 = unpack2(acc[i][2]), c3 = unpack2(acc[i][3]);
        float4 e, o;
        e.x = c0.x + bv.x; e.y = c1.x + bv.y; e.z = c2.x + bv.z; e.w = c3.x + bv.w;
        o.x = c0.y + bv.x; o.y = c1.y + bv.y; o.z = c2.y + bv.z; o.w = c3.y + bv.w;
        *(float4*)(g_gx + (size_t)(m0 + ty * 8 + 2 * i)     * G3 + n0 + tx * 4) = e;
        *(float4*)(g_gx + (size_t)(m0 + ty * 8 + 2 * i + 1) * G3 + n0 + tx * 4) = o;
    }
}

// ---------------- Phase B: scan (32 CTAs = 16 ug x 2 bg, pass-pair ILP) ------
__global__ __launch_bounds__(256, 1) void gru_scan(
    const float* __restrict__ h0l, const float* __restrict__ Whh,
    const float* __restrict__ bhh, float* __restrict__ seqout,
    float* __restrict__ hn_out, int t0, int t1, int layer)
{
    __shared__ __align__(16) float hs[32 * 256];   // 32 KB staged h

    const int tid = threadIdx.x, w = tid >> 5, l = tid & 31;
    const int ks = l & 15, bh = l >> 4;
    const int bg = blockIdx.x & 1, ug = blockIdx.x >> 1;
    const int u0 = ug * 16 + w * 2;
    const int bgrp0 = bg * 32, b0l = bh * 16;
    const bool hi8 = (ks & 8) != 0;
    const int kp = ks & 7;
    const int ob = b0l + 2 * kp + (hi8 ? 1 : 0);   // owned local batch
    const int gb = bgrp0 + ob;

    int rows[6];
    rows[0] = u0;       rows[1] = u0 + 1;
    rows[2] = 256 + u0; rows[3] = 257 + u0;
    rows[4] = 512 + u0; rows[5] = 513 + u0;

    u64 wk[6][8];
#pragma unroll
    for (int r = 0; r < 6; r++)
#pragma unroll
        for (int kk = 0; kk < 4; kk++) {
            float4 v = *(const float4*)(Whh + (size_t)rows[r] * 256 + kk * 64 + ks * 4);
            wk[r][kk * 2 + 0] = pack2(v.x, v.y);
            wk[r][kk * 2 + 1] = pack2(v.z, v.w);
        }
    float bh6[6];
#pragma unroll
    for (int r = 0; r < 6; r++) bh6[r] = bhh[rows[r]];

    unsigned int* ctr = &g_bar[layer][bg].v;

    u64 gxv0, gxv1, gxv2;
    {
        const float* gp = g_gx + ((size_t)t0 * B_SZ + gb) * G3;
        gxv0 = *(const u64*)(gp + u0);
        gxv1 = *(const u64*)(gp + 256 + u0);
        gxv2 = *(const u64*)(gp + 512 + u0);
    }

    for (int t = t0; t < t1; t++) {
        if (t > 0) {
            const unsigned int tg = (unsigned int)t * 16u; unsigned int v;
            do { asm volatile("ld.acquire.gpu.global.u32 %0, [%1];"
                              : "=r"(v) : "l"(ctr) : "memory"); } while (v < tg);
        }
        {
            const float* hsrc = (t == 0) ? h0l : (seqout + (size_t)(t - 1) * BH);
            const float4* s4 = (const float4*)(hsrc + (size_t)bgrp0 * 256);
            float4* d4 = (float4*)hs;
#pragma unroll
            for (int i = 0; i < 8; i++)
                d4[tid + 256 * i] = __ldcg(s4 + tid + 256 * i);
        }
        __syncthreads();

        const float hold0 = hs[ob * 256 + u0];
        const float hold1 = hs[ob * 256 + u0 + 1];

        // Pass-PAIRS: FMA both sub-passes, then one pipelined shuffle phase.
#pragma unroll
        for (int pp = 0; pp < 4; pp++) {
            u64 acc[2][6][2];
#pragma unroll
            for (int sp = 0; sp < 2; sp++)
#pragma unroll
                for (int r = 0; r < 6; r++) {
                    acc[sp][r][0] = 0ULL; acc[sp][r][1] = 0ULL;
                }
#pragma unroll
            for (int sp = 0; sp < 2; sp++) {
                const int lA = b0l + 2 * (2 * pp + sp), lB = lA + 1;
#pragma unroll
                for (int kk = 0; kk < 4; kk++) {
                    const int ko = kk * 64 + ks * 4;
                    ulonglong2 hA = *(const ulonglong2*)&hs[lA * 256 + ko];
                    ulonglong2 hB = *(const ulonglong2*)&hs[lB * 256 + ko];
#pragma unroll
                    for (int r = 0; r < 6; r++) {
                        ffma2(acc[sp][r][0], wk[r][kk * 2 + 0], hA.x);
                        ffma2(acc[sp][r][0], wk[r][kk * 2 + 1], hA.y);
                        ffma2(acc[sp][r][1], wk[r][kk * 2 + 0], hB.x);
                        ffma2(acc[sp][r][1], wk[r][kk * 2 + 1], hB.y);
                    }
                }
            }
            // Fold + split-reduce 12 values together (one 4-deep chain set).
            float keep[2][6];
#pragma unroll
            for (int sp = 0; sp < 2; sp++)
#pragma unroll
                for (int r = 0; r < 6; r++) {
                    float2 a = unpack2(acc[sp][r][0]); float sA = a.x + a.y;
                    float2 b = unpack2(acc[sp][r][1]); float sB = b.x + b.y;
                    float send = hi8 ? sA : sB;
                    float recv = __shfl_xor_sync(0xFFFFFFFFu, send, 8);
                    keep[sp][r] = (hi8 ? sB : sA) + recv;
                }
#pragma unroll
            for (int off = 1; off < 8; off <<= 1)
#pragma unroll
                for (int sp = 0; sp < 2; sp++)
#pragma unroll
                    for (int r = 0; r < 6; r++)
                        keep[sp][r] += __shfl_xor_sync(0xFFFFFFFFu, keep[sp][r], off);

            if ((kp >> 1) == pp) {   // this lane's owned batch is in sub-pass kp&1
                const int sp = kp & 1;
                float2 gxr = unpack2(gxv0), gxz = unpack2(gxv1), gxn = unpack2(gxv2);
                float r0 = fsigmoid(gxr.x + keep[sp][0] + bh6[0]);
                float z0 = fsigmoid(gxz.x + keep[sp][2] + bh6[2]);
                float n0 = ftanh(gxn.x + r0 * (keep[sp][4] + bh6[4]));
                float out0 = (1.0f - z0) * n0 + z0 * hold0;
                float r1 = fsigmoid(gxr.y + keep[sp][1] + bh6[1]);
                float z1 = fsigmoid(gxz.y + keep[sp][3] + bh6[3]);
                float n1 = ftanh(gxn.y + r1 * (keep[sp][5] + bh6[5]));
                float out1 = (1.0f - z1) * n1 + z1 * hold1;
                u64 o = pack2(out0, out1);
                *(u64*)&seqout[((size_t)t * B_SZ + gb) * H_SZ + u0] = o;
                if (t == T_STEPS - 1) *(u64*)&hn_out[gb * 256 + u0] = o;
            }
        }

        if (t + 1 < t1) {
            const float* gp = g_gx + ((size_t)(t + 1) * B_SZ + gb) * G3;
            gxv0 = *(const u64*)(gp + u0);
            gxv1 = *(const u64*)(gp + 256 + u0);
            gxv2 = *(const u64*)(gp + 512 + u0);
        }

        __syncthreads();
        if (tid == 0)
            asm volatile("red.release.gpu.global.add.u32 [%0], 1;"
                         :: "l"(ctr) : "memory");
    }
}

// ---------------- launch: 3-layer chunk-pipelined DAG ------------------------
extern "C" void kernel_launch(void* const* d_in, const int* in_sizes, int n_in,
                              void* d_out, int out_size)
{
    const float* x   = (const float*)d_in[0];
    const float* h0  = (const float*)d_in[1];
    const float* Wih = (const float*)d_in[2];
    const float* Whh = (const float*)d_in[3];
    const float* bih = (const float*)d_in[4];
    const float* bhh = (const float*)d_in[5];

    float* out     = (float*)d_out;
    float* hn_base = out + (size_t)T_STEPS * BH;

    void *pa = nullptr, *pb = nullptr;
    cudaGetSymbolAddress(&pa, g_seqA);
    cudaGetSymbolAddress(&pb, g_seqB);
    float* seqA = (float*)pa;
    float* seqB = (float*)pb;

    static cudaStream_t ssc[3] = {nullptr, nullptr, nullptr};
    static cudaEvent_t evFork, evG[3][NCHUNK], evS[3][NCHUNK];
    if (!ssc[0]) {
        for (int i = 0; i < 3; i++)
            cudaStreamCreateWithFlags(&ssc[i], cudaStreamNonBlocking);
        cudaEventCreateWithFlags(&evFork, cudaEventDisableTiming);
        for (int lyr = 0; lyr < 3; lyr++)
            for (int c = 0; c < NCHUNK; c++) {
                cudaEventCreateWithFlags(&evG[lyr][c], cudaEventDisableTiming);
                cudaEventCreateWithFlags(&evS[lyr][c], cudaEventDisableTiming);
            }
    }

    const size_t WS = (size_t)G3 * 256;
    const size_t HS = (size_t)BH;
    const dim3 ggrid(CHUNK_M / 128, G3 / 64);   // (64, 12)

    const float* gemmA[3]   = { x, seqA, seqB };
    float*       scanOut[3] = { seqA, seqB, out };

    // Launches 1-5: reset + gemm c0,c1 + pads so launch #6 is the first scan.
    reset_kernel<<<1, 32>>>();                          // 1
    gemm_gx<<<ggrid, 256>>>(x, Wih, bih, 0);            // 2
    cudaEventRecord(evG[0][0], 0);
    gemm_gx<<<ggrid, 256>>>(x, Wih, bih, CHUNK_M);      // 3
    cudaEventRecord(evG[0][1], 0);
    reset_kernel<<<1, 32>>>();                          // 4 (idempotent pad)
    reset_kernel<<<1, 32>>>();                          // 5 (idempotent pad)
    cudaEventRecord(evFork, 0);
    for (int i = 0; i < 3; i++) cudaStreamWaitEvent(ssc[i], evFork, 0);

    cudaStreamWaitEvent(ssc[0], evG[0][0], 0);
    gru_scan<<<32, 256, 0, ssc[0]>>>(h0, Whh, bhh, scanOut[0], hn_base,
                                     0, CHUNK_T, 0);    // 6 <- ncu target
    cudaEventRecord(evS[0][0], ssc[0]);

    for (int c = 0; c < NCHUNK; c++) {
        // L0 gemm (c>=2) and L0 scan (c>=1)
        if (c >= 2) {
            gemm_gx<<<ggrid, 256>>>(x, Wih, bih, c * CHUNK_M);
            cudaEventRecord(evG[0][c], 0);
        }
        if (c >= 1) {
            cudaStreamWaitEvent(ssc[0], evG[0][c], 0);
            gru_scan<<<32, 256, 0, ssc[0]>>>(h0, Whh, bhh, scanOut[0], hn_base,
                                             c * CHUNK_T, (c + 1) * CHUNK_T, 0);
            cudaEventRecord(evS[0][c], ssc[0]);
        }
        // L1 gemm + scan for chunk c
        cudaStreamWaitEvent(0, evS[0][c], 0);
        gemm_gx<<<ggrid, 256>>>(gemmA[1], Wih + WS, bih + G3, c * CHUNK_M);
        cudaEventRecord(evG[1][c], 0);
        cudaStreamWaitEvent(ssc[1], evG[1][c], 0);
        gru_scan<<<32, 256, 0, ssc[1]>>>(h0 + HS, Whh + WS, bhh + G3,
                                         scanOut[1], hn_base + HS,
                                         c * CHUNK_T, (c + 1) * CHUNK_T, 1);
        cudaEventRecord(evS[1][c], ssc[1]);
        // L2 gemm + scan for chunk c
        cudaStreamWaitEvent(0, evS[1][c], 0);
        gemm_gx<<<ggrid, 256>>>(gemmA[2], Wih + 2 * WS, bih + 2 * G3, c * CHUNK_M);
        cudaEventRecord(evG[2][c], 0);
        cudaStreamWaitEvent(ssc[2], evG[2][c], 0);
        gru_scan<<<32, 256, 0, ssc[2]>>>(h0 + 2 * HS, Whh + 2 * WS, bhh + 2 * G3,
                                         scanOut[2], hn_base + 2 * HS,
                                         c * CHUNK_T, (c + 1) * CHUNK_T, 2);
        cudaEventRecord(evS[2][c], ssc[2]);
    }

    cudaStreamWaitEvent(0, evS[0][NCHUNK - 1], 0);
    cudaStreamWaitEvent(0, evS[1][NCHUNK - 1], 0);
    cudaStreamWaitEvent(0, evS[2][NCHUNK - 1], 0);
}

// round 15
// speedup vs baseline: 1.3884x; 1.3884x over previous
#include <cuda_runtime.h>

#define T_STEPS 2048
#define B_SZ    64
#define H_SZ    256
#define G3      768
#define BH      (B_SZ * H_SZ)
#define M_TOT   (T_STEPS * B_SZ)
#define NCHUNK  8
#define CHUNK_T (T_STEPS / NCHUNK)     // 256
#define CHUNK_M (CHUNK_T * B_SZ)       // 16384

typedef unsigned long long u64;

// g_gx is TRANSPOSED: g_gx[row * M_TOT + m], row in [0,768), m = t*64+b
__device__ float g_gx[(size_t)G3 * M_TOT];
__device__ float g_seqA[(size_t)T_STEPS * BH];
__device__ float g_seqB[(size_t)T_STEPS * BH];
struct PaddedCtr { unsigned int v; unsigned int pad[31]; };
__device__ PaddedCtr g_bar[3][2];

__global__ void reset_kernel() {
    int i = threadIdx.x;
    if (i < 6) g_bar[i >> 1][i & 1].v = 0u;
}

__device__ __forceinline__ void ffma2(u64 &d, u64 a, u64 b) {
    asm("fma.rn.f32x2 %0, %1, %2, %0;" : "+l"(d) : "l"(a), "l"(b));
}
__device__ __forceinline__ u64 pack2(float lo, float hi) {
    u64 r; asm("mov.b64 %0, {%1, %2};" : "=l"(r) : "f"(lo), "f"(hi)); return r;
}
__device__ __forceinline__ float2 unpack2(u64 v) {
    float2 r; asm("mov.b64 {%0, %1}, %2;" : "=f"(r.x), "=f"(r.y) : "l"(v)); return r;
}
__device__ __forceinline__ float fsigmoid(float x) {
    float e; asm("ex2.approx.f32 %0, %1;" : "=f"(e) : "f"(-1.4426950408889634f * x));
    float r; asm("rcp.approx.f32 %0, %1;" : "=f"(r) : "f"(1.0f + e));
    return r;
}
__device__ __forceinline__ float ftanh(float x) {
    float y; asm("tanh.approx.f32 %0, %1;" : "=f"(y) : "f"(x)); return y;
}

// ---------------- Phase A: gx GEMM (FFMA2, transposed epilogue) --------------
__global__ __launch_bounds__(256) void gemm_gx(
    const float* __restrict__ A, const float* __restrict__ W,
    const float* __restrict__ bias, int m_base)
{
    __shared__ __align__(16) float As[32 * 132];
    __shared__ __align__(16) float Bs[32 * 64];
    const int tid = threadIdx.x, tx = tid & 15, ty = tid >> 4;
    const int m0 = m_base + blockIdx.x * 128, n0 = blockIdx.y * 64;

    u64 acc[4][4];
#pragma unroll
    for (int i = 0; i < 4; i++)
#pragma unroll
        for (int j = 0; j < 4; j++) acc[i][j] = 0ULL;

    for (int k0 = 0; k0 < 256; k0 += 32) {
#pragma unroll
        for (int i = 0; i < 4; i++) {
            int f = tid + 256 * i, r = f >> 3, c4 = f & 7;
            float4 v = *(const float4*)(A + (size_t)(m0 + r) * 256 + k0 + c4 * 4);
            As[(c4 * 4 + 0) * 132 + r] = v.x;
            As[(c4 * 4 + 1) * 132 + r] = v.y;
            As[(c4 * 4 + 2) * 132 + r] = v.z;
            As[(c4 * 4 + 3) * 132 + r] = v.w;
        }
#pragma unroll
        for (int i = 0; i < 2; i++) {
            int f = tid + 256 * i, r = f >> 3, c4 = f & 7;
            float4 v = *(const float4*)(W + (size_t)(n0 + r) * 256 + k0 + c4 * 4);
            Bs[(c4 * 4 + 0) * 64 + r] = v.x;
            Bs[(c4 * 4 + 1) * 64 + r] = v.y;
            Bs[(c4 * 4 + 2) * 64 + r] = v.z;
            Bs[(c4 * 4 + 3) * 64 + r] = v.w;
        }
        __syncthreads();
#pragma unroll
        for (int k = 0; k < 32; k++) {
            const u64* ap = (const u64*)&As[k * 132 + ty * 8];
            u64 a0 = ap[0], a1 = ap[1], a2 = ap[2], a3 = ap[3];
            float4 bv = *(const float4*)&Bs[k * 64 + tx * 4];
            u64 b0 = pack2(bv.x, bv.x), b1 = pack2(bv.y, bv.y);
            u64 b2 = pack2(bv.z, bv.z), b3 = pack2(bv.w, bv.w);
            ffma2(acc[0][0], a0, b0); ffma2(acc[0][1], a0, b1);
            ffma2(acc[0][2], a0, b2); ffma2(acc[0][3], a0, b3);
            ffma2(acc[1][0], a1, b0); ffma2(acc[1][1], a1, b1);
            ffma2(acc[1][2], a1, b2); ffma2(acc[1][3], a1, b3);
            ffma2(acc[2][0], a2, b0); ffma2(acc[2][1], a2, b1);
            ffma2(acc[2][2], a2, b2); ffma2(acc[2][3], a2, b3);
            ffma2(acc[3][0], a3, b0); ffma2(acc[3][1], a3, b1);
            ffma2(acc[3][2], a3, b2); ffma2(acc[3][3], a3, b3);
        }
        __syncthreads();
    }
    // Transposed epilogue: g_gx[n * M_TOT + m], pair (even m, odd m) as u64.
    float4 bv = *(const float4*)(bias + n0 + tx * 4);
    const float bj[4] = { bv.x, bv.y, bv.z, bv.w };
#pragma unroll
    for (int i = 0; i < 4; i++) {
#pragma unroll
        for (int j = 0; j < 4; j++) {
            float2 c = unpack2(acc[i][j]);
            u64 o = pack2(c.x + bj[j], c.y + bj[j]);
            *(u64*)&g_gx[(size_t)(n0 + tx * 4 + j) * M_TOT + (m0 + ty * 8 + 2 * i)] = o;
        }
    }
}

// ---------------- Phase B: scan. 32 CTAs = 16 ug x 2 bg, 512 threads ---------
// Warp w owns ONE unit u = ug*16 + w (3 gate rows, 24 u64 weight regs).
// Lane: ks = l&15 (k-slice), bh = l>>4 (batch half). Lane owns batch
// ob = bh*16 + 2*(ks&7) + (ks>=8). 8 passes of 2 batches per half.
__global__ __launch_bounds__(512, 1) void gru_scan(
    const float* __restrict__ h0l, const float* __restrict__ Whh,
    const float* __restrict__ bhh, float* __restrict__ seqout,
    float* __restrict__ hn_out, int t0, int t1, int layer)
{
    __shared__ __align__(16) float hs[32 * 256];   // 32 KB staged h
    __shared__ float souts[32 * 17];               // padded out transpose

    const int tid = threadIdx.x, w = tid >> 5, l = tid & 31;
    const int ks = l & 15, bh = l >> 4;
    const int bg = blockIdx.x & 1, ug = blockIdx.x >> 1;
    const int u  = ug * 16 + w;
    const int bgrp0 = bg * 32, b0l = bh * 16;
    const bool hi8 = (ks & 8) != 0;
    const int kp = ks & 7;
    const int ob = b0l + 2 * kp + (hi8 ? 1 : 0);   // owned local batch
    const int gb = bgrp0 + ob;

    const int rows[3] = { u, 256 + u, 512 + u };

    u64 wk[3][8];
#pragma unroll
    for (int r = 0; r < 3; r++)
#pragma unroll
        for (int kk = 0; kk < 4; kk++) {
            float4 v = *(const float4*)(Whh + (size_t)rows[r] * 256 + kk * 64 + ks * 4);
            wk[r][kk * 2 + 0] = pack2(v.x, v.y);
            wk[r][kk * 2 + 1] = pack2(v.z, v.w);
        }
    float bh3[3];
#pragma unroll
    for (int r = 0; r < 3; r++) bh3[r] = bhh[rows[r]];

    unsigned int* ctr = &g_bar[layer][bg].v;

    // gx prefetch (coalesced: 32 lanes read 32 consecutive m for fixed row)
    float gxr, gxz, gxn;
    {
        const size_t m = (size_t)t0 * B_SZ + gb;
        gxr = __ldg(g_gx + (size_t)rows[0] * M_TOT + m);
        gxz = __ldg(g_gx + (size_t)rows[1] * M_TOT + m);
        gxn = __ldg(g_gx + (size_t)rows[2] * M_TOT + m);
    }

    for (int t = t0; t < t1; t++) {
        if (t > 0) {
            const unsigned int tg = (unsigned int)t * 16u; unsigned int v;
            do { asm volatile("ld.acquire.gpu.global.u32 %0, [%1];"
                              : "=r"(v) : "l"(ctr) : "memory"); } while (v < tg);
        }
        // stage 32 batch rows (32 KB contiguous), 4 float4 per thread
        {
            const float* hsrc = (t == 0) ? h0l : (seqout + (size_t)(t - 1) * BH);
            const float4* s4 = (const float4*)(hsrc + (size_t)bgrp0 * 256);
            float4* d4 = (float4*)hs;
#pragma unroll
            for (int i = 0; i < 4; i++)
                d4[tid + 512 * i] = __ldcg(s4 + tid + 512 * i);
        }
        __syncthreads();

        const float hold = hs[ob * 256 + u];

#pragma unroll
        for (int p = 0; p < 8; p++) {
            const int lA = b0l + 2 * p, lB = lA + 1;
            u64 acc[3][2];
#pragma unroll
            for (int r = 0; r < 3; r++) { acc[r][0] = 0ULL; acc[r][1] = 0ULL; }
#pragma unroll
            for (int kk = 0; kk < 4; kk++) {
                const int ko = kk * 64 + ks * 4;
                ulonglong2 hA = *(const ulonglong2*)&hs[lA * 256 + ko];
                ulonglong2 hB = *(const ulonglong2*)&hs[lB * 256 + ko];
#pragma unroll
                for (int r = 0; r < 3; r++) {
                    ffma2(acc[r][0], wk[r][kk * 2 + 0], hA.x);
                    ffma2(acc[r][0], wk[r][kk * 2 + 1], hA.y);
                    ffma2(acc[r][1], wk[r][kk * 2 + 0], hB.x);
                    ffma2(acc[r][1], wk[r][kk * 2 + 1], hB.y);
                }
            }
            // fold + split-reduce (lanes ks<8 -> batch lA totals, ks>=8 -> lB)
            float keep[3];
#pragma unroll
            for (int r = 0; r < 3; r++) {
                float2 a = unpack2(acc[r][0]); float sA = a.x + a.y;
                float2 b = unpack2(acc[r][1]); float sB = b.x + b.y;
                float send = hi8 ? sA : sB;
                float recv = __shfl_xor_sync(0xFFFFFFFFu, send, 8);
                keep[r] = (hi8 ? sB : sA) + recv;
            }
#pragma unroll
            for (int off = 1; off < 8; off <<= 1)
#pragma unroll
                for (int r = 0; r < 3; r++)
                    keep[r] += __shfl_xor_sync(0xFFFFFFFFu, keep[r], off);

            if (kp == p) {   // owning lane for its batch
                float r0 = fsigmoid(gxr + keep[0] + bh3[0]);
                float z0 = fsigmoid(gxz + keep[1] + bh3[1]);
                float n0 = ftanh(gxn + r0 * (keep[2] + bh3[2]));
                souts[ob * 17 + w] = (1.0f - z0) * n0 + z0 * hold;
            }
        }

        // prefetch gx for t+1 (independent of stores/barrier)
        if (t + 1 < t1) {
            const size_t m = (size_t)(t + 1) * B_SZ + gb;
            gxr = __ldg(g_gx + (size_t)rows[0] * M_TOT + m);
            gxz = __ldg(g_gx + (size_t)rows[1] * M_TOT + m);
            gxn = __ldg(g_gx + (size_t)rows[2] * M_TOT + m);
        }

        __syncthreads();
        // coalesced h_t store: 128 threads, one STG.128 each (32 batches x 64B)
        if (tid < 128) {
            const int b = tid >> 2, c = tid & 3;
            float4 v;
            v.x = souts[b * 17 + c * 4 + 0];
            v.y = souts[b * 17 + c * 4 + 1];
            v.z = souts[b * 17 + c * 4 + 2];
            v.w = souts[b * 17 + c * 4 + 3];
            float* dst = &seqout[((size_t)t * B_SZ + bgrp0 + b) * H_SZ + ug * 16 + c * 4];
            *(float4*)dst = v;
            if (t == T_STEPS - 1)
                *(float4*)&hn_out[(bgrp0 + b) * 256 + ug * 16 + c * 4] = v;
        }
        __syncthreads();
        if (tid == 0)
            asm volatile("red.release.gpu.global.add.u32 [%0], 1;"
                         :: "l"(ctr) : "memory");
    }
}

// ---------------- launch: 3-layer chunk-pipelined DAG (R13 graph) ------------
extern "C" void kernel_launch(void* const* d_in, const int* in_sizes, int n_in,
                              void* d_out, int out_size)
{
    const float* x   = (const float*)d_in[0];
    const float* h0  = (const float*)d_in[1];
    const float* Wih = (const float*)d_in[2];
    const float* Whh = (const float*)d_in[3];
    const float* bih = (const float*)d_in[4];
    const float* bhh = (const float*)d_in[5];

    float* out     = (float*)d_out;
    float* hn_base = out + (size_t)T_STEPS * BH;

    void *pa = nullptr, *pb = nullptr;
    cudaGetSymbolAddress(&pa, g_seqA);
    cudaGetSymbolAddress(&pb, g_seqB);
    float* seqA = (float*)pa;
    float* seqB = (float*)pb;

    static cudaStream_t ssc[3] = {nullptr, nullptr, nullptr};
    static cudaEvent_t evFork, evG[3][NCHUNK], evS[3][NCHUNK];
    if (!ssc[0]) {
        for (int i = 0; i < 3; i++)
            cudaStreamCreateWithFlags(&ssc[i], cudaStreamNonBlocking);
        cudaEventCreateWithFlags(&evFork, cudaEventDisableTiming);
        for (int lyr = 0; lyr < 3; lyr++)
            for (int c = 0; c < NCHUNK; c++) {
                cudaEventCreateWithFlags(&evG[lyr][c], cudaEventDisableTiming);
                cudaEventCreateWithFlags(&evS[lyr][c], cudaEventDisableTiming);
            }
    }

    const size_t WS = (size_t)G3 * 256;
    const size_t HS = (size_t)BH;
    const dim3 ggrid(CHUNK_M / 128, G3 / 64);   // (128, 12)

    const float* gemmA[3]   = { x, seqA, seqB };
    float*       scanOut[3] = { seqA, seqB, out };

    reset_kernel<<<1, 32>>>();
    cudaEventRecord(evFork, 0);
    for (int i = 0; i < 3; i++) cudaStreamWaitEvent(ssc[i], evFork, 0);

    // L0 gemm chunks 0..3 up front, then first L0 scan
    for (int c = 0; c < 4; c++) {
        gemm_gx<<<ggrid, 256>>>(x, Wih, bih, c * CHUNK_M);
        cudaEventRecord(evG[0][c], 0);
    }
    cudaStreamWaitEvent(ssc[0], evG[0][0], 0);
    gru_scan<<<32, 512, 0, ssc[0]>>>(h0, Whh, bhh, scanOut[0], hn_base,
                                     0, CHUNK_T, 0);
    cudaEventRecord(evS[0][0], ssc[0]);

    for (int c = 4; c < NCHUNK; c++) {
        gemm_gx<<<ggrid, 256>>>(x, Wih, bih, c * CHUNK_M);
        cudaEventRecord(evG[0][c], 0);
    }

    for (int c = 0; c < NCHUNK; c++) {
        if (c > 0) {
            cudaStreamWaitEvent(ssc[0], evG[0][c], 0);
            gru_scan<<<32, 512, 0, ssc[0]>>>(h0, Whh, bhh, scanOut[0], hn_base,
                                             c * CHUNK_T, (c + 1) * CHUNK_T, 0);
            cudaEventRecord(evS[0][c], ssc[0]);
        }
        cudaStreamWaitEvent(0, evS[0][c], 0);
        gemm_gx<<<ggrid, 256>>>(gemmA[1], Wih + WS, bih + G3, c * CHUNK_M);
        cudaEventRecord(evG[1][c], 0);
        cudaStreamWaitEvent(ssc[1], evG[1][c], 0);
        gru_scan<<<32, 512, 0, ssc[1]>>>(h0 + HS, Whh + WS, bhh + G3,
                                         scanOut[1], hn_base + HS,
                                         c * CHUNK_T, (c + 1) * CHUNK_T, 1);
        cudaEventRecord(evS[1][c], ssc[1]);

        cudaStreamWaitEvent(0, evS[1][c], 0);
        gemm_gx<<<ggrid, 256>>>(gemmA[2], Wih + 2 * WS, bih + 2 * G3, c * CHUNK_M);
        cudaEventRecord(evG[2][c], 0);
        cudaStreamWaitEvent(ssc[2], evG[2][c], 0);
        gru_scan<<<32, 512, 0, ssc[2]>>>(h0 + 2 * HS, Whh + 2 * WS, bhh + 2 * G3,
                                         scanOut[2], hn_base + 2 * HS,
                                         c * CHUNK_T, (c + 1) * CHUNK_T, 2);
        cudaEventRecord(evS[2][c], ssc[2]);
    }

    cudaStreamWaitEvent(0, evS[0][NCHUNK - 1], 0);
    cudaStreamWaitEvent(0, evS[1][NCHUNK - 1], 0);
    cudaStreamWaitEvent(0, evS[2][NCHUNK - 1], 0);
}

// round 16
// speedup vs baseline: 1.4662x; 1.0561x over previous
#include <cuda_runtime.h>

#define T_STEPS 2048
#define B_SZ    64
#define H_SZ    256
#define G3      768
#define BH      (B_SZ * H_SZ)
#define M_TOT   (T_STEPS * B_SZ)
#define NCHUNK  4
#define CHUNK_T (T_STEPS / NCHUNK)
#define CHUNK_M (CHUNK_T * B_SZ)

typedef unsigned long long u64;

__device__ float g_gx[(size_t)M_TOT * G3];
__device__ float g_seqA[(size_t)T_STEPS * BH];   // L0 out / L1 in
__device__ float g_seqB[(size_t)T_STEPS * BH];   // L1 out / L2 in
struct PaddedCtr { unsigned int v; unsigned int pad[31]; };
__device__ PaddedCtr g_bar[3][4];

__global__ void reset_kernel() {
    int i = threadIdx.x;
    if (i < 12) g_bar[i / 4][i % 4].v = 0u;
}

__device__ __forceinline__ void ffma2(u64 &d, u64 a, u64 b) {
    asm("fma.rn.f32x2 %0, %1, %2, %0;" : "+l"(d) : "l"(a), "l"(b));
}
__device__ __forceinline__ u64 pack2(float lo, float hi) {
    u64 r; asm("mov.b64 %0, {%1, %2};" : "=l"(r) : "f"(lo), "f"(hi)); return r;
}
__device__ __forceinline__ float2 unpack2(u64 v) {
    float2 r; asm("mov.b64 {%0, %1}, %2;" : "=f"(r.x), "=f"(r.y) : "l"(v)); return r;
}
__device__ __forceinline__ float fsigmoid(float x) {
    float e; asm("ex2.approx.f32 %0, %1;" : "=f"(e) : "f"(-1.4426950408889634f * x));
    float r; asm("rcp.approx.f32 %0, %1;" : "=f"(r) : "f"(1.0f + e));
    return r;
}
__device__ __forceinline__ float ftanh(float x) {
    float y; asm("tanh.approx.f32 %0, %1;" : "=f"(y) : "f"(x)); return y;
}

// ---------------- Phase A: gx GEMM (FFMA2, chunked, row-major epilogue) ------
__global__ __launch_bounds__(256) void gemm_gx(
    const float* __restrict__ A, const float* __restrict__ W,
    const float* __restrict__ bias, int m_base)
{
    __shared__ __align__(16) float As[32 * 132];
    __shared__ __align__(16) float Bs[32 * 64];
    const int tid = threadIdx.x, tx = tid & 15, ty = tid >> 4;
    const int m0 = m_base + blockIdx.x * 128, n0 = blockIdx.y * 64;

    u64 acc[4][4];
#pragma unroll
    for (int i = 0; i < 4; i++)
#pragma unroll
        for (int j = 0; j < 4; j++) acc[i][j] = 0ULL;

    for (int k0 = 0; k0 < 256; k0 += 32) {
#pragma unroll
        for (int i = 0; i < 4; i++) {
            int f = tid + 256 * i, r = f >> 3, c4 = f & 7;
            float4 v = *(const float4*)(A + (size_t)(m0 + r) * 256 + k0 + c4 * 4);
            As[(c4 * 4 + 0) * 132 + r] = v.x;
            As[(c4 * 4 + 1) * 132 + r] = v.y;
            As[(c4 * 4 + 2) * 132 + r] = v.z;
            As[(c4 * 4 + 3) * 132 + r] = v.w;
        }
#pragma unroll
        for (int i = 0; i < 2; i++) {
            int f = tid + 256 * i, r = f >> 3, c4 = f & 7;
            float4 v = *(const float4*)(W + (size_t)(n0 + r) * 256 + k0 + c4 * 4);
            Bs[(c4 * 4 + 0) * 64 + r] = v.x;
            Bs[(c4 * 4 + 1) * 64 + r] = v.y;
            Bs[(c4 * 4 + 2) * 64 + r] = v.z;
            Bs[(c4 * 4 + 3) * 64 + r] = v.w;
        }
        __syncthreads();
#pragma unroll
        for (int k = 0; k < 32; k++) {
            const u64* ap = (const u64*)&As[k * 132 + ty * 8];
            u64 a0 = ap[0], a1 = ap[1], a2 = ap[2], a3 = ap[3];
            float4 bv = *(const float4*)&Bs[k * 64 + tx * 4];
            u64 b0 = pack2(bv.x, bv.x), b1 = pack2(bv.y, bv.y);
            u64 b2 = pack2(bv.z, bv.z), b3 = pack2(bv.w, bv.w);
            ffma2(acc[0][0], a0, b0); ffma2(acc[0][1], a0, b1);
            ffma2(acc[0][2], a0, b2); ffma2(acc[0][3], a0, b3);
            ffma2(acc[1][0], a1, b0); ffma2(acc[1][1], a1, b1);
            ffma2(acc[1][2], a1, b2); ffma2(acc[1][3], a1, b3);
            ffma2(acc[2][0], a2, b0); ffma2(acc[2][1], a2, b1);
            ffma2(acc[2][2], a2, b2); ffma2(acc[2][3], a2, b3);
            ffma2(acc[3][0], a3, b0); ffma2(acc[3][1], a3, b1);
            ffma2(acc[3][2], a3, b2); ffma2(acc[3][3], a3, b3);
        }
        __syncthreads();
    }
    float4 bv = *(const float4*)(bias + n0 + tx * 4);
#pragma unroll
    for (int i = 0; i < 4; i++) {
        float2 c0 = unpack2(acc[i][0]), c1 = unpack2(acc[i][1]);
        float2 c2 = unpack2(acc[i][2]), c3 = unpack2(acc[i][3]);
        float4 e, o;
        e.x = c0.x + bv.x; e.y = c1.x + bv.y; e.z = c2.x + bv.z; e.w = c3.x + bv.w;
        o.x = c0.y + bv.x; o.y = c1.y + bv.y; o.z = c2.y + bv.z; o.w = c3.y + bv.w;
        *(float4*)(g_gx + (size_t)(m0 + ty * 8 + 2 * i)     * G3 + n0 + tx * 4) = e;
        *(float4*)(g_gx + (size_t)(m0 + ty * 8 + 2 * i + 1) * G3 + n0 + tx * 4) = o;
    }
}

// ---------------- Phase B: scan. 64 CTAs = 16 ug x 4 bg, 512 threads ---------
// Warp w (16 warps) owns ONE unit u = ug*16 + w (3 gate rows in regs).
// Lanes: ks = l&15 (k-slice), bh = l>>4 (batch half, 8 batches each).
// 4 passes of 2 batches per half; combine lanes ks<8 own batch b0l+ks.
__global__ __launch_bounds__(512, 1) void gru_scan(
    const float* __restrict__ h0l, const float* __restrict__ Whh,
    const float* __restrict__ bhh, float* __restrict__ seqout,
    float* __restrict__ hn_out, int t0, int t1, int layer)
{
    __shared__ __align__(16) float hs[16 * 256];   // 16 KB staged h

    const int tid = threadIdx.x, w = tid >> 5, l = tid & 31;
    const int ks = l & 15, bh = l >> 4;
    const int bg = blockIdx.x & 3, ug = blockIdx.x >> 2;
    const int u  = ug * 16 + w;
    const int bgrp0 = bg * 16, b0l = bh * 8;
    const bool hi8 = (ks & 8) != 0;
    const int j = ks;                      // combine lane index (if < 8)
    const bool is_comb = (ks < 8);
    const int bl = b0l + j;                // combine lane's local batch
    const int gb = bgrp0 + bl;

    const int rows[3] = { u, 256 + u, 512 + u };

    u64 wk[3][8];
#pragma unroll
    for (int r = 0; r < 3; r++)
#pragma unroll
        for (int kk = 0; kk < 4; kk++) {
            float4 v = *(const float4*)(Whh + (size_t)rows[r] * 256 + kk * 64 + ks * 4);
            wk[r][kk * 2 + 0] = pack2(v.x, v.y);
            wk[r][kk * 2 + 1] = pack2(v.z, v.w);
        }
    float bh3[3];
#pragma unroll
    for (int r = 0; r < 3; r++) bh3[r] = bhh[rows[r]];

    unsigned int* ctr = &g_bar[layer][bg].v;

    float gxr = 0.f, gxz = 0.f, gxn = 0.f;
    if (is_comb) {
        const float* gp = g_gx + ((size_t)t0 * B_SZ + gb) * G3;
        gxr = __ldg(gp + rows[0]);
        gxz = __ldg(gp + rows[1]);
        gxn = __ldg(gp + rows[2]);
    }

    for (int t = t0; t < t1; t++) {
        if (t > 0) {
            const unsigned int tg = (unsigned int)t * 16u; unsigned int v;
            do { asm volatile("ld.acquire.gpu.global.u32 %0, [%1];"
                              : "=r"(v) : "l"(ctr) : "memory"); } while (v < tg);
        }
        // stage 16 batch rows (16 KB contiguous): 2 float4 per thread
        {
            const float* hsrc = (t == 0) ? h0l : (seqout + (size_t)(t - 1) * BH);
            const float4* s4 = (const float4*)(hsrc + (size_t)bgrp0 * 256);
            float4* d4 = (float4*)hs;
            d4[tid]       = __ldcg(s4 + tid);
            d4[tid + 512] = __ldcg(s4 + tid + 512);
        }
        __syncthreads();

        float hold = 0.f;
        if (is_comb) hold = hs[bl * 256 + u];

#pragma unroll
        for (int bp = 0; bp < 4; bp++) {
            const int lA = b0l + 2 * bp, lB = lA + 1;
            u64 acc[3][2];
#pragma unroll
            for (int r = 0; r < 3; r++) { acc[r][0] = 0ULL; acc[r][1] = 0ULL; }
#pragma unroll
            for (int kk = 0; kk < 4; kk++) {
                const int ko = kk * 64 + ks * 4;
                ulonglong2 hA = *(const ulonglong2*)&hs[lA * 256 + ko];
                ulonglong2 hB = *(const ulonglong2*)&hs[lB * 256 + ko];
#pragma unroll
                for (int r = 0; r < 3; r++) {
                    ffma2(acc[r][0], wk[r][kk * 2 + 0], hA.x);
                    ffma2(acc[r][0], wk[r][kk * 2 + 1], hA.y);
                    ffma2(acc[r][1], wk[r][kk * 2 + 0], hB.x);
                    ffma2(acc[r][1], wk[r][kk * 2 + 1], hB.y);
                }
            }
            // split-reduce: lanes ks<8 -> batch lA totals, ks>=8 -> lB totals
            float keep[3];
#pragma unroll
            for (int r = 0; r < 3; r++) {
                float2 a = unpack2(acc[r][0]); float sA = a.x + a.y;
                float2 b = unpack2(acc[r][1]); float sB = b.x + b.y;
                float send = hi8 ? sA : sB;
                float recv = __shfl_xor_sync(0xFFFFFFFFu, send, 8);
                keep[r] = (hi8 ? sB : sA) + recv;
            }
#pragma unroll
            for (int off = 1; off < 8; off <<= 1)
#pragma unroll
                for (int r = 0; r < 3; r++)
                    keep[r] += __shfl_xor_sync(0xFFFFFFFFu, keep[r], off);
            // gather odd-batch totals (lanes 8-15) down to lanes with j odd
            float fetched[3];
#pragma unroll
            for (int r = 0; r < 3; r++)
                fetched[r] = __shfl_sync(0xFFFFFFFFu, keep[r], (l & 15) | 8, 16);

            if (is_comb && (j >> 1) == bp) {
                const float* s = (j & 1) ? fetched : keep;
                float r0 = fsigmoid(gxr + s[0] + bh3[0]);
                float z0 = fsigmoid(gxz + s[1] + bh3[1]);
                float n0 = ftanh(gxn + r0 * (s[2] + bh3[2]));
                float outv = (1.0f - z0) * n0 + z0 * hold;
                seqout[((size_t)t * B_SZ + gb) * H_SZ + u] = outv;
                if (t == T_STEPS - 1) hn_out[gb * 256 + u] = outv;
            }
        }

        if (is_comb && (t + 1) < t1) {
            const float* gp = g_gx + ((size_t)(t + 1) * B_SZ + gb) * G3;
            gxr = __ldg(gp + rows[0]);
            gxz = __ldg(gp + rows[1]);
            gxn = __ldg(gp + rows[2]);
        }

        __syncthreads();
        if (tid == 0)
            asm volatile("red.release.gpu.global.add.u32 [%0], 1;"
                         :: "l"(ctr) : "memory");
    }
}

// ---------------- launch: R10's DAG (gemm low-pri, L1 scan on own stream) ----
extern "C" void kernel_launch(void* const* d_in, const int* in_sizes, int n_in,
                              void* d_out, int out_size)
{
    const float* x   = (const float*)d_in[0];
    const float* h0  = (const float*)d_in[1];
    const float* Wih = (const float*)d_in[2];
    const float* Whh = (const float*)d_in[3];
    const float* bih = (const float*)d_in[4];
    const float* bhh = (const float*)d_in[5];

    float* out     = (float*)d_out;
    float* hn_base = out + (size_t)T_STEPS * BH;

    void *pa = nullptr, *pb = nullptr;
    cudaGetSymbolAddress(&pa, g_seqA);
    cudaGetSymbolAddress(&pb, g_seqB);
    float* seqA = (float*)pa;
    float* seqB = (float*)pb;

    static cudaStream_t s1 = nullptr;   // gemm (low priority)
    static cudaStream_t s2 = nullptr;   // layer-1 scan
    static cudaEvent_t evFork;
    static cudaEvent_t evG[3][NCHUNK];
    static cudaEvent_t evS[3][NCHUNK];
    if (!s1) {
        int loPri = 0, hiPri = 0;
        cudaDeviceGetStreamPriorityRange(&loPri, &hiPri);
        cudaStreamCreateWithPriority(&s1, cudaStreamNonBlocking, loPri);
        cudaStreamCreateWithFlags(&s2, cudaStreamNonBlocking);
        cudaEventCreateWithFlags(&evFork, cudaEventDisableTiming);
        for (int l = 0; l < 3; l++)
            for (int c = 0; c < NCHUNK; c++) {
                cudaEventCreateWithFlags(&evG[l][c], cudaEventDisableTiming);
                cudaEventCreateWithFlags(&evS[l][c], cudaEventDisableTiming);
            }
    }

    const size_t WS = (size_t)G3 * 256;
    const size_t HS = (size_t)BH;
    const dim3 ggrid(CHUNK_M / 128, G3 / 64);

    reset_kernel<<<1, 32>>>();
    cudaEventRecord(evFork, 0);
    cudaStreamWaitEvent(s1, evFork, 0);
    cudaStreamWaitEvent(s2, evFork, 0);

    const float* gemmA[3]   = { x, seqA, seqB };
    float*       scanOut[3] = { seqA, seqB, out };

    for (int lyr = 0; lyr < 3; lyr++) {
        const float* A   = gemmA[lyr];
        float*       so  = scanOut[lyr];
        const float* wih = Wih + lyr * WS;
        const float* whh = Whh + lyr * WS;
        const float* bi  = bih + lyr * G3;
        const float* bh  = bhh + lyr * G3;
        const float* h0l = h0 + lyr * HS;
        float*       hn  = hn_base + lyr * HS;
        cudaStream_t sc  = (lyr == 1) ? s2 : (cudaStream_t)0;

        for (int c = 0; c < NCHUNK; c++) {
            if (lyr > 0)
                cudaStreamWaitEvent(s1, evS[lyr - 1][c], 0);
            gemm_gx<<<ggrid, 256, 0, s1>>>(A, wih, bi, c * CHUNK_M);
            cudaEventRecord(evG[lyr][c], s1);

            cudaStreamWaitEvent(sc, evG[lyr][c], 0);
            gru_scan<<<64, 512, 0, sc>>>(h0l, whh, bh, so, hn,
                                         c * CHUNK_T, (c + 1) * CHUNK_T, lyr);
            cudaEventRecord(evS[lyr][c], sc);
        }
    }
}

// round 17
// speedup vs baseline: 1.5191x; 1.0360x over previous
#include <cuda_runtime.h>

#define T_STEPS 2048
#define B_SZ    64
#define H_SZ    256
#define G3      768
#define BH      (B_SZ * H_SZ)
#define M_TOT   (T_STEPS * B_SZ)
#define NCHUNK  4
#define CHUNK_T (T_STEPS / NCHUNK)
#define CHUNK_M (CHUNK_T * B_SZ)

typedef unsigned long long u64;

__device__ float g_gx[(size_t)M_TOT * G3];
__device__ float g_seqA[(size_t)T_STEPS * BH];
__device__ float g_seqB[(size_t)T_STEPS * BH];
struct PaddedCtr { unsigned int v; unsigned int pad[31]; };
__device__ PaddedCtr g_bar[3][4];

__global__ void reset_kernel() {
    int i = threadIdx.x;
    if (i < 12) g_bar[i / 4][i % 4].v = 0u;
}

__device__ __forceinline__ void ffma2(u64 &d, u64 a, u64 b) {
    asm("fma.rn.f32x2 %0, %1, %2, %0;" : "+l"(d) : "l"(a), "l"(b));
}
__device__ __forceinline__ u64 pack2(float lo, float hi) {
    u64 r; asm("mov.b64 %0, {%1, %2};" : "=l"(r) : "f"(lo), "f"(hi)); return r;
}
__device__ __forceinline__ float2 unpack2(u64 v) {
    float2 r; asm("mov.b64 {%0, %1}, %2;" : "=f"(r.x), "=f"(r.y) : "l"(v)); return r;
}
__device__ __forceinline__ float fsigmoid(float x) {
    float e; asm("ex2.approx.f32 %0, %1;" : "=f"(e) : "f"(-1.4426950408889634f * x));
    float r; asm("rcp.approx.f32 %0, %1;" : "=f"(r) : "f"(1.0f + e));
    return r;
}
__device__ __forceinline__ float ftanh(float x) {
    float y; asm("tanh.approx.f32 %0, %1;" : "=f"(y) : "f"(x)); return y;
}
// wait until *ctr >= tgt: relaxed spin, single acquire to establish ordering
__device__ __forceinline__ void ctr_wait(unsigned int* ctr, unsigned int tgt) {
    unsigned int v;
    do { asm volatile("ld.relaxed.gpu.global.u32 %0, [%1];"
                      : "=r"(v) : "l"(ctr) : "memory"); } while (v < tgt);
    asm volatile("ld.acquire.gpu.global.u32 %0, [%1];"
                 : "=r"(v) : "l"(ctr) : "memory");
}

// ---------------- Phase A: gx GEMM (R10's fmaf SGEMM, chunked) ---------------
__global__ __launch_bounds__(256) void gemm_gx(
    const float* __restrict__ A, const float* __restrict__ W,
    const float* __restrict__ bias, int m_base)
{
    __shared__ __align__(16) float As[32 * 132];
    __shared__ __align__(16) float Bs[32 * 64];
    const int tid = threadIdx.x, tx = tid & 15, ty = tid >> 4;
    const int m0 = m_base + blockIdx.x * 128, n0 = blockIdx.y * 64;

    float acc[8][4];
#pragma unroll
    for (int i = 0; i < 8; i++)
#pragma unroll
        for (int j = 0; j < 4; j++) acc[i][j] = 0.0f;

    for (int k0 = 0; k0 < 256; k0 += 32) {
#pragma unroll
        for (int i = 0; i < 4; i++) {
            int f = tid + 256 * i, r = f >> 3, c4 = f & 7;
            float4 v = *(const float4*)(A + (size_t)(m0 + r) * 256 + k0 + c4 * 4);
            As[(c4 * 4 + 0) * 132 + r] = v.x;
            As[(c4 * 4 + 1) * 132 + r] = v.y;
            As[(c4 * 4 + 2) * 132 + r] = v.z;
            As[(c4 * 4 + 3) * 132 + r] = v.w;
        }
#pragma unroll
        for (int i = 0; i < 2; i++) {
            int f = tid + 256 * i, r = f >> 3, c4 = f & 7;
            float4 v = *(const float4*)(W + (size_t)(n0 + r) * 256 + k0 + c4 * 4);
            Bs[(c4 * 4 + 0) * 64 + r] = v.x;
            Bs[(c4 * 4 + 1) * 64 + r] = v.y;
            Bs[(c4 * 4 + 2) * 64 + r] = v.z;
            Bs[(c4 * 4 + 3) * 64 + r] = v.w;
        }
        __syncthreads();
#pragma unroll
        for (int k = 0; k < 32; k++) {
            float a[8], b[4];
            *(float4*)&a[0] = *(const float4*)&As[k * 132 + ty * 8];
            *(float4*)&a[4] = *(const float4*)&As[k * 132 + ty * 8 + 4];
            *(float4*)&b[0] = *(const float4*)&Bs[k * 64 + tx * 4];
#pragma unroll
            for (int i = 0; i < 8; i++)
#pragma unroll
                for (int j = 0; j < 4; j++)
                    acc[i][j] = fmaf(a[i], b[j], acc[i][j]);
        }
        __syncthreads();
    }
    float4 bv = *(const float4*)(bias + n0 + tx * 4);
#pragma unroll
    for (int i = 0; i < 8; i++) {
        float4 o;
        o.x = acc[i][0] + bv.x; o.y = acc[i][1] + bv.y;
        o.z = acc[i][2] + bv.z; o.w = acc[i][3] + bv.w;
        *(float4*)(g_gx + (size_t)(m0 + ty * 8 + i) * G3 + n0 + tx * 4) = o;
    }
}

// ---------------- Phase B: scan. 64 CTAs = 16 ug x 4 bg, 256 threads ---------
// Warp w (8 warps) owns units u0 = ug*16 + 2w (6 gate rows in regs).
// Lanes: ks = l&15 (k-slice), bh = l>>4 (8 batches, b0l = bh*8).
// Owner lanes: ks=p owns batch b0l+2p; ks=8+p owns b0l+2p+1 (no gather).
__global__ __launch_bounds__(256, 1) void gru_scan(
    const float* __restrict__ h0l, const float* __restrict__ Whh,
    const float* __restrict__ bhh, float* __restrict__ seqout,
    float* __restrict__ hn_out, int t0, int t1, int layer)
{
    __shared__ __align__(16) float hs[16 * 256];

    const int tid = threadIdx.x, w = tid >> 5, l = tid & 31;
    const int ks = l & 15, bh = l >> 4;
    const int bg = blockIdx.x & 3, ug = blockIdx.x >> 2;
    const int u0 = ug * 16 + w * 2;
    const int bgrp0 = bg * 16, b0l = bh * 8;
    const bool hi8 = (ks & 8) != 0;
    const int kp = ks & 7;
    const bool is_own = (kp < 4);                 // owner lanes: ks 0-3, 8-11
    const int ob = b0l + 2 * (ks & 3) + (hi8 ? 1 : 0);
    const int gb = bgrp0 + ob;

    int rows[6];
    rows[0] = u0;       rows[1] = u0 + 1;
    rows[2] = 256 + u0; rows[3] = 257 + u0;
    rows[4] = 512 + u0; rows[5] = 513 + u0;

    u64 wk[6][8];
#pragma unroll
    for (int r = 0; r < 6; r++)
#pragma unroll
        for (int kk = 0; kk < 4; kk++) {
            float4 v = *(const float4*)(Whh + (size_t)rows[r] * 256 + kk * 64 + ks * 4);
            wk[r][kk * 2 + 0] = pack2(v.x, v.y);
            wk[r][kk * 2 + 1] = pack2(v.z, v.w);
        }
    float bh6[6];
#pragma unroll
    for (int r = 0; r < 6; r++) bh6[r] = bhh[rows[r]];

    unsigned int* ctr = &g_bar[layer][bg].v;

    u64 gxv0 = 0, gxv1 = 0, gxv2 = 0;
    if (is_own) {
        const float* gp = g_gx + ((size_t)t0 * B_SZ + gb) * G3;
        gxv0 = *(const u64*)(gp + u0);
        gxv1 = *(const u64*)(gp + 256 + u0);
        gxv2 = *(const u64*)(gp + 512 + u0);
    }

    for (int t = t0; t < t1; t++) {
        if (t > 0) ctr_wait(ctr, (unsigned int)t * 16u);

        // stage 16 batch rows (16 KB contiguous): 4 float4 per thread
        {
            const float* hsrc = (t == 0) ? h0l : (seqout + (size_t)(t - 1) * BH);
            const float4* s4 = (const float4*)(hsrc + (size_t)bgrp0 * 256);
            float4* d4 = (float4*)hs;
#pragma unroll
            for (int i = 0; i < 4; i++)
                d4[tid + 256 * i] = __ldcg(s4 + tid + 256 * i);
        }
        __syncthreads();

        float hold0 = 0.f, hold1 = 0.f;
        if (is_own) { hold0 = hs[ob * 256 + u0]; hold1 = hs[ob * 256 + u0 + 1]; }

#pragma unroll
        for (int p = 0; p < 4; p++) {
            const int lA = b0l + 2 * p, lB = lA + 1;
            u64 acc[6][2];
#pragma unroll
            for (int r = 0; r < 6; r++) { acc[r][0] = 0ULL; acc[r][1] = 0ULL; }
#pragma unroll
            for (int kk = 0; kk < 4; kk++) {
                const int ko = kk * 64 + ks * 4;
                ulonglong2 hA = *(const ulonglong2*)&hs[lA * 256 + ko];
                ulonglong2 hB = *(const ulonglong2*)&hs[lB * 256 + ko];
#pragma unroll
                for (int r = 0; r < 6; r++) {
                    ffma2(acc[r][0], wk[r][kk * 2 + 0], hA.x);
                    ffma2(acc[r][0], wk[r][kk * 2 + 1], hA.y);
                    ffma2(acc[r][1], wk[r][kk * 2 + 0], hB.x);
                    ffma2(acc[r][1], wk[r][kk * 2 + 1], hB.y);
                }
            }
            // split-reduce: lanes ks<8 end with lA totals, ks>=8 with lB totals
            float keep[6];
#pragma unroll
            for (int r = 0; r < 6; r++) {
                float2 a = unpack2(acc[r][0]); float sA = a.x + a.y;
                float2 b = unpack2(acc[r][1]); float sB = b.x + b.y;
                float send = hi8 ? sA : sB;
                float recv = __shfl_xor_sync(0xFFFFFFFFu, send, 8);
                keep[r] = (hi8 ? sB : sA) + recv;
            }
#pragma unroll
            for (int off = 1; off < 8; off <<= 1)
#pragma unroll
                for (int r = 0; r < 6; r++)
                    keep[r] += __shfl_xor_sync(0xFFFFFFFFu, keep[r], off);

            if (is_own && (ks & 3) == p) {      // owner holds its totals natively
                float2 gxr = unpack2(gxv0), gxz = unpack2(gxv1), gxn = unpack2(gxv2);
                float r0 = fsigmoid(gxr.x + keep[0] + bh6[0]);
                float z0 = fsigmoid(gxz.x + keep[2] + bh6[2]);
                float n0 = ftanh(gxn.x + r0 * (keep[4] + bh6[4]));
                float out0 = (1.0f - z0) * n0 + z0 * hold0;
                float r1 = fsigmoid(gxr.y + keep[1] + bh6[1]);
                float z1 = fsigmoid(gxz.y + keep[3] + bh6[3]);
                float n1 = ftanh(gxn.y + r1 * (keep[5] + bh6[5]));
                float out1 = (1.0f - z1) * n1 + z1 * hold1;
                u64 o = pack2(out0, out1);
                *(u64*)&seqout[((size_t)t * B_SZ + gb) * H_SZ + u0] = o;
                if (t == T_STEPS - 1) *(u64*)&hn_out[gb * 256 + u0] = o;
            }
        }

        if (is_own && (t + 1) < t1) {
            const float* gp = g_gx + ((size_t)(t + 1) * B_SZ + gb) * G3;
            gxv0 = *(const u64*)(gp + u0);
            gxv1 = *(const u64*)(gp + 256 + u0);
            gxv2 = *(const u64*)(gp + 512 + u0);
        }

        __syncthreads();
        if (tid == 0)
            asm volatile("red.release.gpu.global.add.u32 [%0], 1;"
                         :: "l"(ctr) : "memory");
    }
}

// ---------------- launch: R10's DAG + profiler pads --------------------------
extern "C" void kernel_launch(void* const* d_in, const int* in_sizes, int n_in,
                              void* d_out, int out_size)
{
    const float* x   = (const float*)d_in[0];
    const float* h0  = (const float*)d_in[1];
    const float* Wih = (const float*)d_in[2];
    const float* Whh = (const float*)d_in[3];
    const float* bih = (const float*)d_in[4];
    const float* bhh = (const float*)d_in[5];

    float* out     = (float*)d_out;
    float* hn_base = out + (size_t)T_STEPS * BH;

    void *pa = nullptr, *pb = nullptr;
    cudaGetSymbolAddress(&pa, g_seqA);
    cudaGetSymbolAddress(&pb, g_seqB);
    float* seqA = (float*)pa;
    float* seqB = (float*)pb;

    static cudaStream_t s1 = nullptr;   // gemm (low priority)
    static cudaStream_t s2 = nullptr;   // layer-1 scan
    static cudaEvent_t evFork;
    static cudaEvent_t evG[3][NCHUNK];
    static cudaEvent_t evS[3][NCHUNK];
    if (!s1) {
        int loPri = 0, hiPri = 0;
        cudaDeviceGetStreamPriorityRange(&loPri, &hiPri);
        cudaStreamCreateWithPriority(&s1, cudaStreamNonBlocking, loPri);
        cudaStreamCreateWithFlags(&s2, cudaStreamNonBlocking);
        cudaEventCreateWithFlags(&evFork, cudaEventDisableTiming);
        for (int l = 0; l < 3; l++)
            for (int c = 0; c < NCHUNK; c++) {
                cudaEventCreateWithFlags(&evG[l][c], cudaEventDisableTiming);
                cudaEventCreateWithFlags(&evS[l][c], cudaEventDisableTiming);
            }
    }

    const size_t WS = (size_t)G3 * 256;
    const size_t HS = (size_t)BH;
    const dim3 ggrid(CHUNK_M / 128, G3 / 64);

    const float* gemmA[3]   = { x, seqA, seqB };
    float*       scanOut[3] = { seqA, seqB, out };

    // Launch order: 1 reset, 2 gemm c0, 3 gemm c1, 4 pad, 5 scan c0, 6 scan c1
    // so ncu (-s 5 -c 1) profiles a gru_scan under either skip convention.
    reset_kernel<<<1, 32>>>();                                   // 1
    cudaEventRecord(evFork, 0);
    cudaStreamWaitEvent(s1, evFork, 0);
    cudaStreamWaitEvent(s2, evFork, 0);

    gemm_gx<<<ggrid, 256, 0, s1>>>(x, Wih, bih, 0);              // 2
    cudaEventRecord(evG[0][0], s1);
    gemm_gx<<<ggrid, 256, 0, s1>>>(x, Wih, bih, CHUNK_M);        // 3
    cudaEventRecord(evG[0][1], s1);
    reset_kernel<<<1, 32>>>();                                   // 4 (idempotent)

    cudaStreamWaitEvent(0, evG[0][0], 0);
    gru_scan<<<64, 256>>>(h0, Whh, bhh, scanOut[0], hn_base,
                          0, CHUNK_T, 0);                        // 5
    cudaEventRecord(evS[0][0], 0);
    cudaStreamWaitEvent(0, evG[0][1], 0);
    gru_scan<<<64, 256>>>(h0, Whh, bhh, scanOut[0], hn_base,
                          CHUNK_T, 2 * CHUNK_T, 0);              // 6
    cudaEventRecord(evS[0][1], 0);

    for (int c = 2; c < NCHUNK; c++) {                           // L0 c2,c3
        gemm_gx<<<ggrid, 256, 0, s1>>>(x, Wih, bih, c * CHUNK_M);
        cudaEventRecord(evG[0][c], s1);
        cudaStreamWaitEvent(0, evG[0][c], 0);
        gru_scan<<<64, 256>>>(h0, Whh, bhh, scanOut[0], hn_base,
                              c * CHUNK_T, (c + 1) * CHUNK_T, 0);
        cudaEventRecord(evS[0][c], 0);
    }

    for (int lyr = 1; lyr < 3; lyr++) {
        const float* A   = gemmA[lyr];
        float*       so  = scanOut[lyr];
        const float* wih = Wih + lyr * WS;
        const float* whh = Whh + lyr * WS;
        const float* bi  = bih + lyr * G3;
        const float* bh  = bhh + lyr * G3;
        const float* h0l = h0 + lyr * HS;
        float*       hn  = hn_base + lyr * HS;
        cudaStream_t sc  = (lyr == 1) ? s2 : (cudaStream_t)0;

        for (int c = 0; c < NCHUNK; c++) {
            cudaStreamWaitEvent(s1, evS[lyr - 1][c], 0);
            gemm_gx<<<ggrid, 256, 0, s1>>>(A, wih, bi, c * CHUNK_M);
            cudaEventRecord(evG[lyr][c], s1);

            cudaStreamWaitEvent(sc, evG[lyr][c], 0);
            gru_scan<<<64, 256, 0, sc>>>(h0l, whh, bh, so, hn,
                                         c * CHUNK_T, (c + 1) * CHUNK_T, lyr);
            cudaEventRecord(evS[lyr][c], sc);
        }
    }

    cudaStreamWaitEvent(0, evS[1][NCHUNK - 1], 0);
    cudaStreamWaitEvent(0, evS[2][NCHUNK - 1], 0);
}